// round 12
// baseline (speedup 1.0000x reference)
#include <cuda_runtime.h>
#include <cstdint>

#define NN 50000
#define NE 500000
#define HH 128

// ---------------- scratch (device globals; no cudaMalloc allowed) ----------------
__device__ float g_U[NN * HH];
__device__ float g_V[NN * HH];
__device__ float g_S[NN * HH];          // segment sum of relu(h)
__device__ float g_INTRA[NN * HH];
__device__ float g_HID[NN * 2 * HH];
__device__ float g_XA[NN * HH];
__device__ float g_XB[NN * HH];
__device__ float g_POS[NN * 3];
__device__ float g_POSACC[NN * 3];
__device__ float g_DEG[NN];
__device__ float g_DINV[NN];
__device__ float g_BMASK[NN];
__device__ float g_C[HH * 256];         // W2 @ aW1
__device__ float g_D[256];              // b2 @ aW1 + ab1
__device__ int   g_SRC[NE];
__device__ int   g_DST[NE];

// ---------------- mma helper (raw fp32 bits; tf32 HW truncates mantissa) ----------
__device__ __forceinline__ void mma8(float c[4],
                                     unsigned a0, unsigned a1, unsigned a2, unsigned a3,
                                     unsigned b0, unsigned b1) {
    asm("mma.sync.aligned.m16n8k8.row.col.f32.tf32.tf32.f32 "
        "{%0,%1,%2,%3},{%4,%5,%6,%7},{%8,%9},{%0,%1,%2,%3};"
        : "+f"(c[0]), "+f"(c[1]), "+f"(c[2]), "+f"(c[3])
        : "r"(a0), "r"(a1), "r"(a2), "r"(a3), "r"(b0), "r"(b1));
}

// -------- index normalization: handles harness storing edge_index as int32 OR int64
__global__ void convert_idx(const int* __restrict__ ei32, int* __restrict__ SRC,
                            int* __restrict__ DST)
{
    bool is64 = (ei32[1] == 0 && ei32[3] == 0 && ei32[5] == 0 && ei32[7] == 0);
    int e = blockIdx.x * blockDim.x + threadIdx.x;
    if (e >= NE) return;
    if (is64) {
        const long long* e64 = (const long long*)ei32;
        SRC[e] = (int)e64[e];
        DST[e] = (int)e64[NE + e];
    } else {
        SRC[e] = ei32[e];
        DST[e] = ei32[NE + e];
    }
}

// ---------------- tf32 GEMM: 128(M) x 128(N) block, 256 threads (node side) -------
#define SA_STR 20
#define SB_STR 136
__global__ void __launch_bounds__(256) gemm_tf32(
    const float* __restrict__ A, const float* __restrict__ A2,
    const float* __restrict__ B, const float* __restrict__ bias,
    float* __restrict__ Cout, int M, int K, int Ncols,
    int reluFlag, const float* __restrict__ rowscale, const float* __restrict__ rowmask)
{
    __shared__ unsigned sA[128 * SA_STR];
    __shared__ unsigned sB[16 * SB_STR];
    const int bm = blockIdx.y * 128;
    const int bn = blockIdx.x * 128;
    const int tid = threadIdx.x;
    const int lane = tid & 31;
    const int warp = tid >> 5;
    const int wm = warp >> 1;   // 0..3
    const int wn = warp & 1;    // 0..1

    const int arow = tid >> 1;
    const int ac0  = (tid & 1) << 3;
    const int brow = tid >> 5;
    const int bn4  = (tid & 31) << 2;

    float acc[2][8][4];
#pragma unroll
    for (int i = 0; i < 2; i++)
#pragma unroll
        for (int j = 0; j < 8; j++)
#pragma unroll
            for (int q = 0; q < 4; q++) acc[i][j][q] = 0.f;

    uint4 pa0, pa1, pb0, pb1;
    {
        int grow = bm + arow;
        pa0 = make_uint4(0, 0, 0, 0); pa1 = make_uint4(0, 0, 0, 0);
        if (grow < M) {
            int gk = ac0;
            const float* s;
            if (A2) s = (gk < HH) ? (A + (long)grow * HH + gk) : (A2 + (long)grow * HH + gk - HH);
            else    s = A + (long)grow * K + gk;
            pa0 = *(const uint4*)s;
            pa1 = *(const uint4*)(s + 4);
        }
        pb0 = *(const uint4*)(B + (long)brow * Ncols + bn + bn4);
        pb1 = *(const uint4*)(B + (long)(brow + 8) * Ncols + bn + bn4);
    }

    for (int k0 = 0; k0 < K; k0 += 16) {
        *(uint4*)&sA[arow * SA_STR + ac0]     = pa0;
        *(uint4*)&sA[arow * SA_STR + ac0 + 4] = pa1;
        *(uint4*)&sB[brow * SB_STR + bn4]       = pb0;
        *(uint4*)&sB[(brow + 8) * SB_STR + bn4] = pb1;
        __syncthreads();

        int kn = k0 + 16;
        if (kn < K) {
            int grow = bm + arow;
            pa0 = make_uint4(0, 0, 0, 0); pa1 = make_uint4(0, 0, 0, 0);
            if (grow < M) {
                int gk = kn + ac0;
                const float* s;
                if (A2) s = (gk < HH) ? (A + (long)grow * HH + gk) : (A2 + (long)grow * HH + gk - HH);
                else    s = A + (long)grow * K + gk;
                pa0 = *(const uint4*)s;
                pa1 = *(const uint4*)(s + 4);
            }
            pb0 = *(const uint4*)(B + (long)(kn + brow) * Ncols + bn + bn4);
            pb1 = *(const uint4*)(B + (long)(kn + brow + 8) * Ncols + bn + bn4);
        }

#pragma unroll
        for (int ks = 0; ks < 2; ks++) {
            const int kk = ks * 8 + (lane & 3);
            unsigned a[2][4];
#pragma unroll
            for (int it = 0; it < 2; it++) {
                int rb = wm * 32 + it * 16 + (lane >> 2);
                a[it][0] = sA[rb * SA_STR + kk];
                a[it][1] = sA[(rb + 8) * SA_STR + kk];
                a[it][2] = sA[rb * SA_STR + kk + 4];
                a[it][3] = sA[(rb + 8) * SA_STR + kk + 4];
            }
#pragma unroll
            for (int jt = 0; jt < 8; jt++) {
                int nb = wn * 64 + jt * 8 + (lane >> 2);
                unsigned b0 = sB[kk * SB_STR + nb];
                unsigned b1 = sB[(kk + 4) * SB_STR + nb];
                mma8(acc[0][jt], a[0][0], a[0][1], a[0][2], a[0][3], b0, b1);
                mma8(acc[1][jt], a[1][0], a[1][1], a[1][2], a[1][3], b0, b1);
            }
        }
        __syncthreads();
    }

#pragma unroll
    for (int it = 0; it < 2; it++) {
        int row0 = bm + wm * 32 + it * 16 + (lane >> 2);
#pragma unroll
        for (int h = 0; h < 2; h++) {
            int row = row0 + h * 8;
            if (row >= M) continue;
            float rs = rowscale ? rowscale[row] : 1.f;
            float rm = rowmask ? rowmask[row] : 1.f;
#pragma unroll
            for (int jt = 0; jt < 8; jt++) {
                int col = bn + wn * 64 + jt * 8 + ((lane & 3) << 1);
                float v0 = acc[it][jt][h * 2 + 0] * rs;
                float v1 = acc[it][jt][h * 2 + 1] * rs;
                if (bias) { v0 += bias[col] * rm; v1 += bias[col + 1] * rm; }
                if (reluFlag) { v0 = fmaxf(v0, 0.f); v1 = fmaxf(v1, 0.f); }
                *(float2*)(Cout + (long)row * Ncols + col) = make_float2(v0, v1);
            }
        }
    }
}

// ---------------- PERSISTENT fused edge kernel -------------------------------------
// 148 CTAs (1/SM), each stages Cm (128x256) into shared ONCE, then loops over
// 128-edge tiles:
//  phase 1 : H = relu(ea@W1c + b1 + U[dst] + V[src]) -> shared sH (streamed W1c)
//  phase 1b: S[dst] += H (red.global.add.v4.f32, if doS)
//  phase 2 : w = (relu(H@Cm + D)) . aW2 -- pure LDS+MMA from persistent sCm, NO syncs
//  tail    : equivariant pos accumulation into PACC
// Dynamic shared layout (bytes):
//  sCm  @ 0      : 128*264*4 = 135168  (persistent phase-2 B; stride%32==8 conflict-free)
//  sH   @ 135168 : 128*132*4 = 67584
//  sAe  @ 202752 : 128*20*4  = 10240
//  sB1  @ 212992 : 16*136*4  = 8704
//  sDst @ 221696 (512), sSrc @ 222208 (512), red @ 222720 (1024)  -> total 223744
#define SH_STR 132
#define CM_STR 264
#define FE_SMEM 223744
__global__ void __launch_bounds__(256, 1) fused_edge_persist(
    const float* __restrict__ EA, const float* __restrict__ W1c,
    const float* __restrict__ b1,
    const float* __restrict__ U, const float* __restrict__ V,
    const int* __restrict__ SRC, const int* __restrict__ DST,
    const float* __restrict__ Cm, const float* __restrict__ D,
    const float* __restrict__ aW2, const float* __restrict__ ab2,
    const float* __restrict__ POS,
    float* __restrict__ S, float* __restrict__ PACC, int doS, int ntiles)
{
    extern __shared__ char smem[];
    unsigned* sCm = (unsigned*)smem;
    float*    sH  = (float*)(smem + 135168);
    unsigned* sAe = (unsigned*)(smem + 202752);
    unsigned* sB1 = (unsigned*)(smem + 212992);
    int*   sDst = (int*)(smem + 221696);
    int*   sSrc = (int*)(smem + 222208);
    float (*red)[2] = (float(*)[2])(smem + 222720);

    const int tid = threadIdx.x;
    const int lane = tid & 31;
    const int warp = tid >> 5;
    const int wm = warp >> 1;   // 0..3
    const int wn = warp & 1;    // 0..1

    // ---- stage Cm once (raw bits) ----
    for (int i = tid * 4; i < 128 * 256; i += 256 * 4) {
        int r = i >> 8, c = i & 255;
        *(uint4*)&sCm[r * CM_STR + c] = *(const uint4*)(Cm + r * 256 + c);
    }
    __syncthreads();

    const int arow = tid >> 1;          // 0..127
    const int ac0  = (tid & 1) << 3;    // 0 or 8
    const int brow = tid >> 5;          // 0..7 (+8)
    const int bn4  = (tid & 31) << 2;   // 0..124

    for (int t = blockIdx.x; t < ntiles; t += gridDim.x) {
        const int bm = t * 128;

        // stage edge indices (protected from prior-tile tail by loop-end sync)
        if (tid < 128) {
            int e = bm + tid;
            sDst[tid] = (e < NE) ? DST[e] : 0;
            sSrc[tid] = (e < NE) ? SRC[e] : 0;
        }

        // ---------------- phase 1: H = EA @ W1c (128 x 128, K=128) ----------------
        {
            float acc[2][8][4];
#pragma unroll
            for (int i = 0; i < 2; i++)
#pragma unroll
                for (int j = 0; j < 8; j++)
#pragma unroll
                    for (int q = 0; q < 4; q++) acc[i][j][q] = 0.f;

            uint4 pa0, pa1, pb0, pb1;
            {
                int grow = bm + arow;
                pa0 = make_uint4(0, 0, 0, 0); pa1 = make_uint4(0, 0, 0, 0);
                if (grow < NE) {
                    const float* s = EA + (long)grow * HH + ac0;
                    pa0 = *(const uint4*)s;
                    pa1 = *(const uint4*)(s + 4);
                }
                pb0 = *(const uint4*)(W1c + (long)brow * HH + bn4);
                pb1 = *(const uint4*)(W1c + (long)(brow + 8) * HH + bn4);
            }

            for (int k0 = 0; k0 < 128; k0 += 16) {
                *(uint4*)&sAe[arow * SA_STR + ac0]     = pa0;
                *(uint4*)&sAe[arow * SA_STR + ac0 + 4] = pa1;
                *(uint4*)&sB1[brow * SB_STR + bn4]       = pb0;
                *(uint4*)&sB1[(brow + 8) * SB_STR + bn4] = pb1;
                __syncthreads();

                int kn = k0 + 16;
                if (kn < 128) {
                    int grow = bm + arow;
                    pa0 = make_uint4(0, 0, 0, 0); pa1 = make_uint4(0, 0, 0, 0);
                    if (grow < NE) {
                        const float* s = EA + (long)grow * HH + kn + ac0;
                        pa0 = *(const uint4*)s;
                        pa1 = *(const uint4*)(s + 4);
                    }
                    pb0 = *(const uint4*)(W1c + (long)(kn + brow) * HH + bn4);
                    pb1 = *(const uint4*)(W1c + (long)(kn + brow + 8) * HH + bn4);
                }

#pragma unroll
                for (int ks = 0; ks < 2; ks++) {
                    const int kk = ks * 8 + (lane & 3);
                    unsigned a[2][4];
#pragma unroll
                    for (int it = 0; it < 2; it++) {
                        int rb = wm * 32 + it * 16 + (lane >> 2);
                        a[it][0] = sAe[rb * SA_STR + kk];
                        a[it][1] = sAe[(rb + 8) * SA_STR + kk];
                        a[it][2] = sAe[rb * SA_STR + kk + 4];
                        a[it][3] = sAe[(rb + 8) * SA_STR + kk + 4];
                    }
#pragma unroll
                    for (int jt = 0; jt < 8; jt++) {
                        int nb = wn * 64 + jt * 8 + (lane >> 2);
                        unsigned b0 = sB1[kk * SB_STR + nb];
                        unsigned b1r = sB1[(kk + 4) * SB_STR + nb];
                        mma8(acc[0][jt], a[0][0], a[0][1], a[0][2], a[0][3], b0, b1r);
                        mma8(acc[1][jt], a[1][0], a[1][1], a[1][2], a[1][3], b0, b1r);
                    }
                }
                __syncthreads();
            }

            // epilogue: + b1 + U[dst] + V[src], relu, -> sH
#pragma unroll
            for (int it = 0; it < 2; it++) {
#pragma unroll
                for (int h = 0; h < 2; h++) {
                    int r = wm * 32 + it * 16 + (lane >> 2) + h * 8;
                    bool valid = (bm + r) < NE;
                    int d = sDst[r], s = sSrc[r];
#pragma unroll
                    for (int jt = 0; jt < 8; jt++) {
                        int c = wn * 64 + jt * 8 + ((lane & 3) << 1);
                        float v0 = 0.f, v1 = 0.f;
                        if (valid) {
                            float2 uu = *(const float2*)(U + (long)d * HH + c);
                            float2 vv = *(const float2*)(V + (long)s * HH + c);
                            v0 = fmaxf(acc[it][jt][h * 2 + 0] + b1[c]     + uu.x + vv.x, 0.f);
                            v1 = fmaxf(acc[it][jt][h * 2 + 1] + b1[c + 1] + uu.y + vv.y, 0.f);
                        }
                        *(float2*)&sH[r * SH_STR + c] = make_float2(v0, v1);
                    }
                }
            }
        }
        __syncthreads();

        // ---------------- phase 1b: S[dst] += H (vector red) ----------------
        if (doS) {
            int r = tid >> 1;
            int cb = (tid & 1) << 6;   // 0 or 64
            if (bm + r < NE) {
                float* base = S + (long)sDst[r] * HH + cb;
                const float* hrow = sH + r * SH_STR + cb;
#pragma unroll
                for (int p = 0; p < 16; p++) {
                    float4 v = *(const float4*)(hrow + p * 4);
                    if (v.x != 0.f || v.y != 0.f || v.z != 0.f || v.w != 0.f) {
                        asm volatile("red.global.add.v4.f32 [%0], {%1,%2,%3,%4};"
                                     :: "l"(base + p * 4), "f"(v.x), "f"(v.y), "f"(v.z), "f"(v.w)
                                     : "memory");
                    }
                }
            }
        }

        // ---------------- phase 2: w = (relu(H@Cm + D)) . aW2 -- syncless ----------
        float ws[2][2];
        ws[0][0] = ws[0][1] = ws[1][0] = ws[1][1] = 0.f;
#pragma unroll 1
        for (int ch = 0; ch < 2; ch++) {
            float acc2[2][8][4];
#pragma unroll
            for (int i = 0; i < 2; i++)
#pragma unroll
                for (int j = 0; j < 8; j++)
#pragma unroll
                    for (int q = 0; q < 4; q++) acc2[i][j][q] = 0.f;

#pragma unroll 1
            for (int k0 = 0; k0 < 128; k0 += 16) {
#pragma unroll
                for (int ks = 0; ks < 2; ks++) {
                    const int kkg = k0 + ks * 8 + (lane & 3);
                    unsigned a[2][4];
#pragma unroll
                    for (int it = 0; it < 2; it++) {
                        int rb = wm * 32 + it * 16 + (lane >> 2);
                        a[it][0] = __float_as_uint(sH[rb * SH_STR + kkg]);
                        a[it][1] = __float_as_uint(sH[(rb + 8) * SH_STR + kkg]);
                        a[it][2] = __float_as_uint(sH[rb * SH_STR + kkg + 4]);
                        a[it][3] = __float_as_uint(sH[(rb + 8) * SH_STR + kkg + 4]);
                    }
#pragma unroll
                    for (int jt = 0; jt < 8; jt++) {
                        int nb = ch * 128 + wn * 64 + jt * 8 + (lane >> 2);
                        unsigned b0 = sCm[kkg * CM_STR + nb];
                        unsigned b1r = sCm[(kkg + 4) * CM_STR + nb];
                        mma8(acc2[0][jt], a[0][0], a[0][1], a[0][2], a[0][3], b0, b1r);
                        mma8(acc2[1][jt], a[1][0], a[1][1], a[1][2], a[1][3], b0, b1r);
                    }
                }
            }

            // fold this half into per-row partial dots
#pragma unroll
            for (int it = 0; it < 2; it++) {
#pragma unroll
                for (int jt = 0; jt < 8; jt++) {
                    int col = ch * 128 + wn * 64 + jt * 8 + ((lane & 3) << 1);
                    float d0 = D[col], d1 = D[col + 1];
                    float w0 = aW2[col], w1 = aW2[col + 1];
                    ws[it][0] += fmaxf(acc2[it][jt][0] + d0, 0.f) * w0
                               + fmaxf(acc2[it][jt][1] + d1, 0.f) * w1;
                    ws[it][1] += fmaxf(acc2[it][jt][2] + d0, 0.f) * w0
                               + fmaxf(acc2[it][jt][3] + d1, 0.f) * w1;
                }
            }
        }

        // cross-lane reduce (over lane&3) and stage per-row partials
#pragma unroll
        for (int it = 0; it < 2; it++) {
#pragma unroll
            for (int h = 0; h < 2; h++) {
                float s = ws[it][h];
                s += __shfl_xor_sync(0xffffffffu, s, 1);
                s += __shfl_xor_sync(0xffffffffu, s, 2);
                if ((lane & 3) == 0) {
                    int r = wm * 32 + it * 16 + (lane >> 2) + h * 8;
                    red[r][wn] = s;
                }
            }
        }
        __syncthreads();

        // tail: fused equivariant pos accumulation
        if (tid < 128) {
            int e = bm + tid;
            if (e < NE) {
                float w = red[tid][0] + red[tid][1] + ab2[0];
                int src = sSrc[tid], dst = sDst[tid];
                float rx = POS[src * 3 + 0] - POS[dst * 3 + 0];
                float ry = POS[src * 3 + 1] - POS[dst * 3 + 1];
                float rz = POS[src * 3 + 2] - POS[dst * 3 + 2];
                float dist = sqrtf(rx * rx + ry * ry + rz * rz);
                float sc = w / dist;
                atomicAdd(&PACC[dst * 3 + 0], sc * rx);
                atomicAdd(&PACC[dst * 3 + 1], sc * ry);
                atomicAdd(&PACC[dst * 3 + 2], sc * rz);
            }
        }
        __syncthreads();   // protect sDst/sSrc/sH/red before next tile overwrites
    }
}

// ---------------- small per-layer prep: C = W2@aW1, D = b2@aW1 + ab1 --------------
__global__ void prep_kernel(const float* __restrict__ W2, const float* __restrict__ aW1,
                            const float* __restrict__ b2, const float* __restrict__ ab1,
                            float* __restrict__ C, float* __restrict__ D)
{
    int j = threadIdx.x;   // 0..255
    int k = blockIdx.x;    // 0..128
    if (k < 128) {
        float s = 0.f;
#pragma unroll 8
        for (int t = 0; t < 128; t++) s += W2[k * 128 + t] * aW1[t * 256 + j];
        C[k * 256 + j] = s;
    } else {
        float s = ab1[j];
#pragma unroll 8
        for (int t = 0; t < 128; t++) s += b2[t] * aW1[t * 256 + j];
        D[j] = s;
    }
}

// ---------------- degree / denom -------------------------------------------------
__global__ void deg_kernel(const int* __restrict__ DST, float* __restrict__ DEG)
{
    int e = blockIdx.x * blockDim.x + threadIdx.x;
    if (e < NE) atomicAdd(&DEG[DST[e]], 1.f);
}

__global__ void dinv_kernel(const float* __restrict__ DEG, float* __restrict__ DINV,
                            float* __restrict__ BM)
{
    int n = blockIdx.x * blockDim.x + threadIdx.x;
    if (n >= NN) return;
    float d = DEG[n];
    DINV[n] = 1.f / fmaxf(d, 1.f);
    BM[n] = (d > 0.f) ? 1.f : 0.f;
}

__global__ void pos_apply_kernel(float* __restrict__ POS, const float* __restrict__ PACC,
                                 const float* __restrict__ DINV, float* __restrict__ outp)
{
    int n = blockIdx.x * blockDim.x + threadIdx.x;
    if (n >= NN) return;
    float di = DINV[n];
#pragma unroll
    for (int i = 0; i < 3; i++) {
        float v = POS[n * 3 + i] + PACC[n * 3 + i] * di;
        POS[n * 3 + i] = v;
        if (outp) outp[n * 3 + i] = v;
    }
}

// ---------------- host ------------------------------------------------------------
extern "C" void kernel_launch(void* const* d_in, const int* in_sizes, int n_in,
                              void* d_out, int out_size)
{
    const float* x        = (const float*)d_in[0];
    const int*   ei32     = (const int*)d_in[1];
    const float* ea       = (const float*)d_in[2];
    const float* pos      = (const float*)d_in[3];
    const float* mW1      = (const float*)d_in[4];
    const float* mb1      = (const float*)d_in[5];
    const float* mW2      = (const float*)d_in[6];
    const float* mb2      = (const float*)d_in[7];
    const float* aW1      = (const float*)d_in[8];
    const float* ab1      = (const float*)d_in[9];
    const float* aW2      = (const float*)d_in[10];
    const float* ab2      = (const float*)d_in[11];
    const float* nW1      = (const float*)d_in[12];
    const float* nb1      = (const float*)d_in[13];
    const float* nW2      = (const float*)d_in[14];
    const float* nb2      = (const float*)d_in[15];
    float* outp = (float*)d_out;

    float *pU, *pV, *pS, *pINTRA, *pHID, *pXA, *pXB, *pPOS, *pPACC;
    float *pDEG, *pDINV, *pBM, *pC, *pD;
    int *pSRC, *pDST;
    cudaGetSymbolAddress((void**)&pU, g_U);
    cudaGetSymbolAddress((void**)&pV, g_V);
    cudaGetSymbolAddress((void**)&pS, g_S);
    cudaGetSymbolAddress((void**)&pINTRA, g_INTRA);
    cudaGetSymbolAddress((void**)&pHID, g_HID);
    cudaGetSymbolAddress((void**)&pXA, g_XA);
    cudaGetSymbolAddress((void**)&pXB, g_XB);
    cudaGetSymbolAddress((void**)&pPOS, g_POS);
    cudaGetSymbolAddress((void**)&pPACC, g_POSACC);
    cudaGetSymbolAddress((void**)&pDEG, g_DEG);
    cudaGetSymbolAddress((void**)&pDINV, g_DINV);
    cudaGetSymbolAddress((void**)&pBM, g_BMASK);
    cudaGetSymbolAddress((void**)&pC, g_C);
    cudaGetSymbolAddress((void**)&pD, g_D);
    cudaGetSymbolAddress((void**)&pSRC, g_SRC);
    cudaGetSymbolAddress((void**)&pDST, g_DST);

    static int attr_done = 0;
    if (!attr_done) {
        cudaFuncSetAttribute(fused_edge_persist,
                             cudaFuncAttributeMaxDynamicSharedMemorySize, FE_SMEM);
        attr_done = 1;
    }

    cudaMemcpyAsync(pPOS, pos, (size_t)NN * 3 * sizeof(float), cudaMemcpyDeviceToDevice);
    convert_idx<<<(NE + 255) / 256, 256>>>(ei32, pSRC, pDST);
    cudaMemsetAsync(pDEG, 0, (size_t)NN * sizeof(float));
    deg_kernel<<<(NE + 255) / 256, 256>>>(pDST, pDEG);
    dinv_kernel<<<(NN + 255) / 256, 256>>>(pDEG, pDINV, pBM);

    const float* xc = x;
    float* xn = pXA;
    const int ntiles = (NE + 127) / 128;

    for (int l = 0; l < 3; l++) {
        const int last = (l == 2);
        const float* mW1l = mW1 + (long)l * 384 * 128;
        const float* mb1l = mb1 + (long)l * 128;
        const float* mW2l = mW2 + (long)l * 128 * 128;
        const float* mb2l = mb2 + (long)l * 128;
        const float* aW1l = aW1 + (long)l * 128 * 256;
        const float* ab1l = ab1 + (long)l * 256;
        const float* aW2l = aW2 + (long)l * 256;
        const float* ab2l = ab2 + (long)l;
        const float* nW1l = nW1 + (long)l * 256 * 256;
        const float* nb1l = nb1 + (long)l * 256;
        const float* nW2l = nW2 + (long)l * 256 * 128;
        const float* nb2l = nb2 + (long)l * 128;

        if (!last) cudaMemsetAsync(pS, 0, (size_t)NN * HH * sizeof(float));
        cudaMemsetAsync(pPACC, 0, (size_t)NN * 3 * sizeof(float));

        prep_kernel<<<129, 256>>>(mW2l, aW1l, mb2l, ab1l, pC, pD);

        dim3 gN(1, (NN + 127) / 128);
        gemm_tf32<<<gN, 256>>>(xc, nullptr, mW1l, nullptr, pU, NN, 128, 128, 0, nullptr, nullptr);
        gemm_tf32<<<gN, 256>>>(xc, nullptr, mW1l + 128 * 128, nullptr, pV, NN, 128, 128, 0, nullptr, nullptr);

        fused_edge_persist<<<148, 256, FE_SMEM>>>(
            ea, mW1l + 256 * 128, mb1l, pU, pV, pSRC, pDST,
            pC, pD, aW2l, ab2l, pPOS, pS, pPACC, last ? 0 : 1, ntiles);

        pos_apply_kernel<<<(NN + 255) / 256, 256>>>(pPOS, pPACC, pDINV, last ? outp : nullptr);

        if (!last) {
            gemm_tf32<<<gN, 256>>>(pS, nullptr, mW2l, mb2l, pINTRA, NN, 128, 128, 0, pDINV, pBM);
            dim3 gH(2, (NN + 127) / 128);
            gemm_tf32<<<gH, 256>>>(xc, pINTRA, nW1l, nb1l, pHID, NN, 256, 256, 1, nullptr, nullptr);
            gemm_tf32<<<gN, 256>>>(pHID, nullptr, nW2l, nb2l, xn, NN, 256, 128, 0, nullptr, nullptr);
            xc = xn;
            xn = (xn == pXA) ? pXB : pXA;
        }
    }
}